// round 2
// baseline (speedup 1.0000x reference)
#include <cuda_runtime.h>

// Painting: sequential alpha-composite of N RGBA layers onto a ones canvas.
// canvas = canvas*(1-a) + a*poly,  a = poly[alpha]*0.8
// One thread per 4 consecutive pixels (float4 per channel), full recurrence
// in registers. Manual unroll-by-4 with front-batched loads: 16 independent
// LDG.128 in flight per thread per loop body to push DRAM past the
// latency-BW knee (grid gives only ~13.5 warps/SM, so MLP must come from
// within the warp).

#define OPACITY 0.8f

__device__ __forceinline__ void composite4(float4& c0, float4& c1,
                                           float4& c2, float4& c3,
                                           const float4& p0, const float4& p1,
                                           const float4& p2, const float4& p3)
{
    float ax = p3.x * OPACITY;
    float ay = p3.y * OPACITY;
    float az = p3.z * OPACITY;
    float aw = p3.w * OPACITY;

    c0.x = fmaf(ax, p0.x - c0.x, c0.x);
    c0.y = fmaf(ay, p0.y - c0.y, c0.y);
    c0.z = fmaf(az, p0.z - c0.z, c0.z);
    c0.w = fmaf(aw, p0.w - c0.w, c0.w);

    c1.x = fmaf(ax, p1.x - c1.x, c1.x);
    c1.y = fmaf(ay, p1.y - c1.y, c1.y);
    c1.z = fmaf(az, p1.z - c1.z, c1.z);
    c1.w = fmaf(aw, p1.w - c1.w, c1.w);

    c2.x = fmaf(ax, p2.x - c2.x, c2.x);
    c2.y = fmaf(ay, p2.y - c2.y, c2.y);
    c2.z = fmaf(az, p2.z - c2.z, c2.z);
    c2.w = fmaf(aw, p2.w - c2.w, c2.w);

    c3.x = fmaf(ax, p3.x - c3.x, c3.x);
    c3.y = fmaf(ay, p3.y - c3.y, c3.y);
    c3.z = fmaf(az, p3.z - c3.z, c3.z);
    c3.w = fmaf(aw, p3.w - c3.w, c3.w);
}

__global__ __launch_bounds__(256)
void painting_kernel(const float4* __restrict__ polys,
                     float4* __restrict__ out,
                     int planeQuads,   // HW/4
                     int N)            // assumed divisible by 4
{
    int p = blockIdx.x * blockDim.x + threadIdx.x;
    if (p >= planeQuads) return;

    float4 c0 = make_float4(1.f, 1.f, 1.f, 1.f);
    float4 c1 = c0, c2 = c0, c3 = c0;

    const float4* base = polys + p;
    const long long layerStride = 4LL * planeQuads;

    for (int i = 0; i < N; i += 4) {
        float4 P[4][4];
        // ---- load phase: 16 independent LDG.128, all issued before use ----
#pragma unroll
        for (int u = 0; u < 4; ++u) {
            const float4* l = base + (long long)(i + u) * layerStride;
            P[u][0] = __ldcs(l);
            P[u][1] = __ldcs(l + planeQuads);
            P[u][2] = __ldcs(l + 2 * planeQuads);
            P[u][3] = __ldcs(l + 3 * planeQuads);
        }
        // ---- compute phase ----
#pragma unroll
        for (int u = 0; u < 4; ++u)
            composite4(c0, c1, c2, c3, P[u][0], P[u][1], P[u][2], P[u][3]);
    }

    out[p]                  = c0;
    out[planeQuads + p]     = c1;
    out[2 * planeQuads + p] = c2;
    out[3 * planeQuads + p] = c3;
}

extern "C" void kernel_launch(void* const* d_in, const int* in_sizes, int n_in,
                              void* d_out, int out_size)
{
    const float4* polys = (const float4*)d_in[0];
    float4* out = (float4*)d_out;

    const int H = 512, W = 512;
    const int HW = H * W;
    const int planeQuads = HW / 4;              // 65536
    const int N = in_sizes[0] / (4 * HW);       // 128

    const int threads = 256;
    const int blocks = (planeQuads + threads - 1) / threads;  // 256
    painting_kernel<<<blocks, threads>>>(polys, out, planeQuads, N);
}

// round 3
// speedup vs baseline: 1.1314x; 1.1314x over previous
#include <cuda_runtime.h>

// Painting: sequential alpha-composite of N RGBA layers onto a ones canvas.
// canvas = canvas*(1-a) + a*poly,  a = poly[alpha]*0.8
//
// R3: one thread per PIXEL (scalar loads). 262144 threads -> ~55 warps/SM,
// 4x the occupancy of the float4 version. Warp-wide, each LDG.32 covers a
// full 128B line of a channel plane (planar layout), so coalescing and total
// traffic are unchanged; the extra warps supply the memory-level parallelism
// that register pressure prevented within a single warp.

#define OPACITY 0.8f

__global__ __launch_bounds__(256)
void painting_kernel(const float* __restrict__ polys,
                     float* __restrict__ out,
                     int HW,
                     int N)            // assumed divisible by 4
{
    int p = blockIdx.x * blockDim.x + threadIdx.x;
    if (p >= HW) return;

    float c0 = 1.f, c1 = 1.f, c2 = 1.f, c3 = 1.f;

    const float* base = polys + p;
    const long long layerStride = 4LL * HW;

    for (int i = 0; i < N; i += 4) {
        float P[4][4];
        // load phase: 16 independent LDG.32 (fits easily in registers)
#pragma unroll
        for (int u = 0; u < 4; ++u) {
            const float* l = base + (long long)(i + u) * layerStride;
            P[u][0] = __ldcs(l);
            P[u][1] = __ldcs(l + HW);
            P[u][2] = __ldcs(l + 2 * HW);
            P[u][3] = __ldcs(l + 3 * HW);
        }
        // compute phase
#pragma unroll
        for (int u = 0; u < 4; ++u) {
            float a = P[u][3] * OPACITY;
            c0 = fmaf(a, P[u][0] - c0, c0);
            c1 = fmaf(a, P[u][1] - c1, c1);
            c2 = fmaf(a, P[u][2] - c2, c2);
            c3 = fmaf(a, P[u][3] - c3, c3);
        }
    }

    out[p]          = c0;
    out[HW + p]     = c1;
    out[2 * HW + p] = c2;
    out[3 * HW + p] = c3;
}

extern "C" void kernel_launch(void* const* d_in, const int* in_sizes, int n_in,
                              void* d_out, int out_size)
{
    const float* polys = (const float*)d_in[0];
    float* out = (float*)d_out;

    const int H = 512, W = 512;
    const int HW = H * W;                       // 262144
    const int N = in_sizes[0] / (4 * HW);       // 128

    const int threads = 256;
    const int blocks = (HW + threads - 1) / threads;  // 1024
    painting_kernel<<<blocks, threads>>>(polys, out, HW, N);
}